// round 13
// baseline (speedup 1.0000x reference)
#include <cuda_runtime.h>
#include <cuda_bf16.h>

#define B_    32
#define PRE_  2048
#define POST_ 2048
#define KSPL  32

typedef unsigned int u32;

// ---- static device scratch ---------------------------------------------------
__device__ float g_part[KSPL * B_ * POST_];                   // fwd split-K partials (8 MB)
__device__ __align__(16) __nv_bfloat16 g_Apack[POST_ * 128];  // dw A operand (K-major)
__device__ __align__(16) __nv_bfloat16 g_Bpack[PRE_  * 128];  // dw B operand (K-major)

struct alignas(8) BV4 { __nv_bfloat16 v[4]; };

// ---- helpers -----------------------------------------------------------------
__device__ __forceinline__ u32 smem_u32(const void* p) {
    u32 a;
    asm("{ .reg .u64 t; cvta.to.shared.u64 t, %1; cvt.u32.u64 %0, t; }" : "=r"(a) : "l"(p));
    return a;
}
__device__ __forceinline__ void mma16816(float* d, const u32* a, const u32* b) {
    asm volatile(
        "mma.sync.aligned.m16n8k16.row.col.f32.bf16.bf16.f32 "
        "{%0,%1,%2,%3}, {%4,%5,%6,%7}, {%8,%9}, {%0,%1,%2,%3};"
        : "+f"(d[0]), "+f"(d[1]), "+f"(d[2]), "+f"(d[3])
        : "r"(a[0]), "r"(a[1]), "r"(a[2]), "r"(a[3]), "r"(b[0]), "r"(b[1]));
}
__device__ __forceinline__ void mma1688tf32(float* d, const u32* a, u32 b0, u32 b1) {
    asm volatile(
        "mma.sync.aligned.m16n8k8.row.col.f32.tf32.tf32.f32 "
        "{%0,%1,%2,%3}, {%4,%5,%6,%7}, {%8,%9}, {%0,%1,%2,%3};"
        : "+f"(d[0]), "+f"(d[1]), "+f"(d[2]), "+f"(d[3])
        : "r"(a[0]), "r"(a[1]), "r"(a[2]), "r"(a[3]), "r"(b0), "r"(b1));
}
__device__ __forceinline__ u32 cvt_tf32(float v) {
    u32 r;
    asm("cvt.rna.tf32.f32 %0, %1;" : "=r"(r) : "f"(v));
    return r;
}
#define CP_ASYNC16(dst, src) \
    asm volatile("cp.async.cg.shared.global [%0], [%1], 16;" :: "r"(dst), "l"(src) : "memory")
#define CP_COMMIT()  asm volatile("cp.async.commit_group;" ::: "memory")
#define CP_WAIT(n)   asm volatile("cp.async.wait_group %0;" :: "n"(n) : "memory")

// =============================================================================
// kA: forward split-K partials of i = x @ W^T via tf32 HMMA, 2-split W in regs.
// grid (POST/128 = 16, KSPL=32), 128 thr (4 warps). CTA: p-tile 128, k-range 64
// (2 chunks of 32, both cp.async-prefetched up front). Warp tile 32b x 32p
// (mf=2, nf=4): per k8 step 8 A-LDS + 8 W-LDS feed 16 MMAs (LDS/MMA = 1).
// smem 45.5 KB static -> ~5 CTAs/SM; 512 CTAs, single wave.
// =============================================================================
#define KA_RAWS 36                      // raw fp32 row stride (bank-spread pad)
#define KA_XSS  68                      // x tf32 row stride (u32)

__global__ __launch_bounds__(128, 4) void kA(const float* __restrict__ x,
                                             const float* __restrict__ W) {
    __shared__ float raw[2][128 * KA_RAWS];   // 2 x 18432 B
    __shared__ u32   xs[32 * KA_XSS];         // 8704 B

    const int tid = threadIdx.x, wid = tid >> 5, lane = tid & 31;
    const int gid = lane >> 2, tig = lane & 3;
    const int p0 = blockIdx.x * 128;
    const int k0 = blockIdx.y * 64;
    const u32 rawb = smem_u32(&raw[0][0]);

    // prefetch both 32-k W chunks (128 rows x 32 floats each)
#pragma unroll
    for (int c = 0; c < 2; ++c) {
        const int kb = k0 + c * 32;
#pragma unroll
        for (int g = 0; g < 8; ++g)
            CP_ASYNC16(rawb + (u32)(c * 128 * KA_RAWS + tid * KA_RAWS + g * 4) * 4,
                       W + (size_t)(p0 + tid) * PRE_ + kb + g * 4);
        CP_COMMIT();
    }

    // stage x tile [32 b][64 k] as exact tf32
    {
        const int b = tid >> 2, kseg = (tid & 3) * 16;
        const float4* xr = reinterpret_cast<const float4*>(x + b * PRE_ + k0 + kseg);
#pragma unroll
        for (int j = 0; j < 4; ++j) {
            float4 v = xr[j];
            xs[b * KA_XSS + kseg + j * 4 + 0] = cvt_tf32(v.x);
            xs[b * KA_XSS + kseg + j * 4 + 1] = cvt_tf32(v.y);
            xs[b * KA_XSS + kseg + j * 4 + 2] = cvt_tf32(v.z);
            xs[b * KA_XSS + kseg + j * 4 + 3] = cvt_tf32(v.w);
        }
    }

    float acc[2][4][4];   // [mf(b half)][nf(8p group)][reg]
#pragma unroll
    for (int i = 0; i < 2; ++i)
#pragma unroll
        for (int j = 0; j < 4; ++j)
#pragma unroll
            for (int r = 0; r < 4; ++r) acc[i][j][r] = 0.0f;

#pragma unroll
    for (int c = 0; c < 2; ++c) {
        if (c == 0) { CP_WAIT(1); } else { CP_WAIT(0); }
        __syncthreads();
        const float* rb = &raw[c][0];
#pragma unroll
        for (int ks = 0; ks < 4; ++ks) {
            const int kc = ks * 8;
            const int kx = c * 32 + kc;
            // A fragments (x, exact tf32)
            u32 a[2][4];
#pragma unroll
            for (int mf = 0; mf < 2; ++mf) {
                const int r0 = mf * 16 + gid;
                a[mf][0] = xs[r0 * KA_XSS + kx + tig];
                a[mf][1] = xs[(r0 + 8) * KA_XSS + kx + tig];
                a[mf][2] = xs[r0 * KA_XSS + kx + tig + 4];
                a[mf][3] = xs[(r0 + 8) * KA_XSS + kx + tig + 4];
            }
            // B fragments: 4 p-groups, fp32 -> (hi, lo) tf32 in registers
#pragma unroll
            for (int nf = 0; nf < 4; ++nf) {
                const int n = wid * 32 + nf * 8 + gid;
                float w0 = rb[n * KA_RAWS + kc + tig];
                float w1 = rb[n * KA_RAWS + kc + tig + 4];
                u32 h0 = cvt_tf32(w0), h1 = cvt_tf32(w1);
                u32 l0 = cvt_tf32(w0 - __uint_as_float(h0));
                u32 l1 = cvt_tf32(w1 - __uint_as_float(h1));
                mma1688tf32(acc[0][nf], a[0], h0, h1);
                mma1688tf32(acc[1][nf], a[1], h0, h1);
                mma1688tf32(acc[0][nf], a[0], l0, l1);
                mma1688tf32(acc[1][nf], a[1], l0, l1);
            }
        }
        if (c == 0) __syncthreads();
    }

    // epilogue: partials g_part[split][b][p]
    float* pp = g_part + (size_t)blockIdx.y * (B_ * POST_);
#pragma unroll
    for (int mf = 0; mf < 2; ++mf)
#pragma unroll
        for (int nf = 0; nf < 4; ++nf) {
            const int p = p0 + wid * 32 + nf * 8 + tig * 2;
            const int b = mf * 16 + gid;
            *reinterpret_cast<float2*>(&pp[(size_t)b * POST_ + p]) =
                make_float2(acc[mf][nf][0], acc[mf][nf][1]);
            *reinterpret_cast<float2*>(&pp[(size_t)(b + 8) * POST_ + p]) =
                make_float2(acc[mf][nf][2], acc[mf][nf][3]);
        }
}

// =============================================================================
// kBP: fused reduce + spike + traces + operand packing. grid 64 x 256 thr,
// 32 columns of both packs per block.
//  A[p][kk]: 0-31 & 32-63 = spike ; 64-95 = hi(tqn) ; 96-127 = lo(tqn)
//  B[q][kk]: 0-31 = hi(tp) ; 32-63 = lo(tp) ; 64-95 & 96-127 = x
// =============================================================================
__global__ __launch_bounds__(256) void kBP(const float* __restrict__ x,
                                           const float* __restrict__ tpre,
                                           const float* __restrict__ tpost,
                                           float* __restrict__ out_spike) {
    __shared__ float sp[32][36], tq[32][36], tp[32][36], xsm[32][36];
    const int tid = threadIdx.x;
    const int c0 = blockIdx.x * 32;

#pragma unroll
    for (int r = 0; r < 4; ++r) {
        int u = tid + r * 256;
        int b = u >> 5, j = u & 31;
        int gi = b * 2048 + c0 + j;
        float s = 0.0f;
#pragma unroll
        for (int k = 0; k < KSPL; ++k) s += g_part[(size_t)k * (B_ * POST_) + gi];
        float spike = (s >= 1.0f) ? 1.0f : 0.0f;
        out_spike[gi] = spike;
        sp[b][j] = spike;
        tq[b][j] = -(0.5f * tpost[gi] + spike);
        float xv = x[gi];
        xsm[b][j] = xv;
        tp[b][j]  = 0.5f * tpre[gi] + xv;
    }
    __syncthreads();

#pragma unroll
    for (int r = 0; r < 4; ++r) {
        int u = tid + r * 256;
        int rr = u >> 5, c4 = u & 31;
        int reg = c4 >> 3, bs = (c4 & 7) * 4;
        BV4 oA, oB;
#pragma unroll
        for (int t = 0; t < 4; ++t) {
            int b = bs + t;
            if (reg < 2) oA.v[t] = __float2bfloat16(sp[b][rr]);
            else {
                float v = tq[b][rr];
                __nv_bfloat16 h = __float2bfloat16(v);
                oA.v[t] = (reg == 2) ? h : __float2bfloat16(v - __bfloat162float(h));
            }
            if (reg >= 2) oB.v[t] = __float2bfloat16(xsm[b][rr]);
            else {
                float v = tp[b][rr];
                __nv_bfloat16 h = __float2bfloat16(v);
                oB.v[t] = (reg == 0) ? h : __float2bfloat16(v - __bfloat162float(h));
            }
        }
        *reinterpret_cast<BV4*>(&g_Apack[(size_t)(c0 + rr) * 128 + c4 * 4]) = oA;
        *reinterpret_cast<BV4*>(&g_Bpack[(size_t)(c0 + rr) * 128 + c4 * 4]) = oB;
    }
}

// =============================================================================
// kC: dw = clip(W) * (Apack @ Bpack^T), K=128 bf16 HMMA.
// grid (32, 16) = 512 CTAs, 256 thr. Tile 64p x 128q; warps 2(p) x 4(q).
// Three cp.async groups: pack K-half0 / pack K-half1 / W tile. MMA on half0
// overlaps the half1 + W loads; W consumed only in the epilogue.
// =============================================================================
#define KC_AS   136                         // pack tile stride (bf16)
#define KC_AB   (64 * KC_AS * 2)            // 17408
#define KC_BB   (128 * KC_AS * 2)           // 34816
#define KC_WS   132                         // W tile stride (fp32)
#define KC_WB   (64 * KC_WS * 4)            // 33792
#define KC_SMEM (KC_AB + KC_BB + KC_WB)     // 86016

__global__ __launch_bounds__(256, 2) void kC(const float* __restrict__ W,
                                             float* __restrict__ dw) {
    extern __shared__ char smc[];
    __nv_bfloat16* As = reinterpret_cast<__nv_bfloat16*>(smc);
    __nv_bfloat16* Bs = reinterpret_cast<__nv_bfloat16*>(smc + KC_AB);
    float* Wsm = reinterpret_cast<float*>(smc + KC_AB + KC_BB);
    const u32 sb = smem_u32(smc);

    const int tid = threadIdx.x, wid = tid >> 5, lane = tid & 31;
    const int gid = lane >> 2, tig = lane & 3;
    const int pw = wid >> 2, qw = wid & 3;
    const int p0 = blockIdx.x * 64, q0 = blockIdx.y * 128;

    // group 1: pack K-half 0 (bytes 0..127 of each 256B row)
#pragma unroll
    for (int i = 0; i < 2; ++i) {
        int u = tid + i * 256;
        int row = u >> 3, g = u & 7;
        CP_ASYNC16(sb + (u32)(row * KC_AS * 2 + g * 16),
                   g_Apack + (size_t)(p0 + row) * 128 + g * 8);
    }
#pragma unroll
    for (int i = 0; i < 4; ++i) {
        int u = tid + i * 256;
        int row = u >> 3, g = u & 7;
        CP_ASYNC16(sb + KC_AB + (u32)(row * KC_AS * 2 + g * 16),
                   g_Bpack + (size_t)(q0 + row) * 128 + g * 8);
    }
    CP_COMMIT();
    // group 2: pack K-half 1
#pragma unroll
    for (int i = 0; i < 2; ++i) {
        int u = tid + i * 256;
        int row = u >> 3, g = (u & 7) + 8;
        CP_ASYNC16(sb + (u32)(row * KC_AS * 2 + g * 16),
                   g_Apack + (size_t)(p0 + row) * 128 + g * 8);
    }
#pragma unroll
    for (int i = 0; i < 4; ++i) {
        int u = tid + i * 256;
        int row = u >> 3, g = (u & 7) + 8;
        CP_ASYNC16(sb + KC_AB + (u32)(row * KC_AS * 2 + g * 16),
                   g_Bpack + (size_t)(q0 + row) * 128 + g * 8);
    }
    CP_COMMIT();
    // group 3: W tile (epilogue only)
#pragma unroll
    for (int i = 0; i < 8; ++i) {
        int u = tid + i * 256;
        int row = u >> 5, g = u & 31;
        CP_ASYNC16(sb + KC_AB + KC_BB + (u32)(row * KC_WS + g * 4) * 4,
                   W + (size_t)(p0 + row) * PRE_ + q0 + g * 4);
    }
    CP_COMMIT();

    float acc[2][4][4];
#pragma unroll
    for (int i = 0; i < 2; ++i)
#pragma unroll
        for (int j = 0; j < 4; ++j)
#pragma unroll
            for (int r = 0; r < 4; ++r) acc[i][j][r] = 0.0f;

#pragma unroll
    for (int h = 0; h < 2; ++h) {
        if (h == 0) { CP_WAIT(2); } else { CP_WAIT(1); }
        __syncthreads();
#pragma unroll
        for (int kk = 0; kk < 4; ++kk) {
            const int kc = h * 64 + kk * 16 + tig * 2;
            u32 a[2][4];
#pragma unroll
            for (int mf = 0; mf < 2; ++mf) {
                const int r0 = pw * 32 + mf * 16 + gid;
                a[mf][0] = *reinterpret_cast<const u32*>(&As[r0 * KC_AS + kc]);
                a[mf][1] = *reinterpret_cast<const u32*>(&As[(r0 + 8) * KC_AS + kc]);
                a[mf][2] = *reinterpret_cast<const u32*>(&As[r0 * KC_AS + kc + 8]);
                a[mf][3] = *reinterpret_cast<const u32*>(&As[(r0 + 8) * KC_AS + kc + 8]);
            }
#pragma unroll
            for (int nf = 0; nf < 4; ++nf) {
                const int n = qw * 32 + nf * 8 + gid;
                u32 b[2];
                b[0] = *reinterpret_cast<const u32*>(&Bs[n * KC_AS + kc]);
                b[1] = *reinterpret_cast<const u32*>(&Bs[n * KC_AS + kc + 8]);
                mma16816(acc[0][nf], a[0], b);
                mma16816(acc[1][nf], a[1], b);
            }
        }
    }

    CP_WAIT(0);          // W tile landed (fully overlapped with MMA)
    __syncthreads();

#pragma unroll
    for (int mf = 0; mf < 2; ++mf)
#pragma unroll
        for (int nf = 0; nf < 4; ++nf) {
            const int pl = pw * 32 + mf * 16 + gid;
            const int ql = qw * 32 + nf * 8 + tig * 2;
            float2 w0 = *reinterpret_cast<const float2*>(&Wsm[pl * KC_WS + ql]);
            float2 w1 = *reinterpret_cast<const float2*>(&Wsm[(pl + 8) * KC_WS + ql]);
            float2 o0, o1;
            o0.x = fminf(fmaxf(w0.x, -1.f), 1.f) * acc[mf][nf][0];
            o0.y = fminf(fmaxf(w0.y, -1.f), 1.f) * acc[mf][nf][1];
            o1.x = fminf(fmaxf(w1.x, -1.f), 1.f) * acc[mf][nf][2];
            o1.y = fminf(fmaxf(w1.y, -1.f), 1.f) * acc[mf][nf][3];
            *reinterpret_cast<float2*>(&dw[(size_t)(p0 + pl) * PRE_ + q0 + ql]) = o0;
            *reinterpret_cast<float2*>(&dw[(size_t)(p0 + pl + 8) * PRE_ + q0 + ql]) = o1;
        }
}

// =============================================================================
extern "C" void kernel_launch(void* const* d_in, const int* in_sizes, int n_in,
                              void* d_out, int out_size) {
    const float* x     = (const float*)d_in[0];   // [32, 2048]
    const float* W     = (const float*)d_in[1];   // [2048, 2048]
    const float* tpre  = (const float*)d_in[2];   // [32, 2048]
    const float* tpost = (const float*)d_in[3];   // [32, 2048]
    float* out     = (float*)d_out;
    float* spike_o = out;                         // [32, 2048]
    float* dw_o    = out + B_ * POST_;            // [2048, 2048]

    cudaFuncSetAttribute(kC, cudaFuncAttributeMaxDynamicSharedMemorySize, KC_SMEM);

    kA<<<dim3(POST_ / 128, KSPL), 128>>>(x, W);
    kBP<<<64, 256>>>(x, tpre, tpost, spike_o);
    kC<<<dim3(POST_ / 64, PRE_ / 128), 256, KC_SMEM>>>(W, dw_o);
}

// round 15
// speedup vs baseline: 1.1115x; 1.1115x over previous
#include <cuda_runtime.h>
#include <cuda_bf16.h>

#define B_    32
#define PRE_  2048
#define POST_ 2048
#define KSPL  32

typedef unsigned int u32;

// ---- static device scratch ---------------------------------------------------
__device__ float g_part[KSPL * B_ * POST_];                   // fwd split-K partials (8 MB)
__device__ __align__(16) __nv_bfloat16 g_Apack[POST_ * 128];  // dw A operand (K-major)
__device__ __align__(16) __nv_bfloat16 g_Bpack[PRE_  * 128];  // dw B operand (K-major)

struct alignas(8) BV4 { __nv_bfloat16 v[4]; };

// ---- helpers -----------------------------------------------------------------
__device__ __forceinline__ u32 smem_u32(const void* p) {
    u32 a;
    asm("{ .reg .u64 t; cvta.to.shared.u64 t, %1; cvt.u32.u64 %0, t; }" : "=r"(a) : "l"(p));
    return a;
}
__device__ __forceinline__ void mma16816(float* d, const u32* a, const u32* b) {
    asm volatile(
        "mma.sync.aligned.m16n8k16.row.col.f32.bf16.bf16.f32 "
        "{%0,%1,%2,%3}, {%4,%5,%6,%7}, {%8,%9}, {%0,%1,%2,%3};"
        : "+f"(d[0]), "+f"(d[1]), "+f"(d[2]), "+f"(d[3])
        : "r"(a[0]), "r"(a[1]), "r"(a[2]), "r"(a[3]), "r"(b[0]), "r"(b[1]));
}
__device__ __forceinline__ void mma1688tf32(float* d, const u32* a, u32 b0, u32 b1) {
    asm volatile(
        "mma.sync.aligned.m16n8k8.row.col.f32.tf32.tf32.f32 "
        "{%0,%1,%2,%3}, {%4,%5,%6,%7}, {%8,%9}, {%0,%1,%2,%3};"
        : "+f"(d[0]), "+f"(d[1]), "+f"(d[2]), "+f"(d[3])
        : "r"(a[0]), "r"(a[1]), "r"(a[2]), "r"(a[3]), "r"(b0), "r"(b1));
}
__device__ __forceinline__ u32 cvt_tf32(float v) {
    u32 r;
    asm("cvt.rna.tf32.f32 %0, %1;" : "=r"(r) : "f"(v));
    return r;
}
#define CP_ASYNC16(dst, src) \
    asm volatile("cp.async.cg.shared.global [%0], [%1], 16;" :: "r"(dst), "l"(src) : "memory")
#define CP_COMMIT()  asm volatile("cp.async.commit_group;" ::: "memory")
#define CP_WAIT(n)   asm volatile("cp.async.wait_group %0;" :: "n"(n) : "memory")

// =============================================================================
// kA: forward split-K partials of i = x @ W^T via tf32 HMMA, 2-split W in regs.
// grid (POST/64 = 32, KSPL=32) = 1024 CTAs, 128 thr (4 warps).
// CTA: p-tile 64, k-range 64 (2 chunks of 32, both prefetched up front).
// Warp tile 32b x 16p (mf=2, nf=2): per k8 step 8 A-LDS + 4 W-LDS -> 8 MMAs.
// smem 27 KB, <=64 regs -> ~7 CTAs/SM avg, occ ~43% (2x R13 warps).
// =============================================================================
#define KA_RAWS 36                      // raw fp32 row stride (bank-spread pad)
#define KA_XSS  68                      // x tf32 row stride (u32)

__global__ __launch_bounds__(128, 8) void kA(const float* __restrict__ x,
                                             const float* __restrict__ W) {
    __shared__ float raw[2][64 * KA_RAWS];   // 2 x 9216 B
    __shared__ u32   xs[32 * KA_XSS];        // 8704 B

    const int tid = threadIdx.x, wid = tid >> 5, lane = tid & 31;
    const int gid = lane >> 2, tig = lane & 3;
    const int p0 = blockIdx.x * 64;
    const int k0 = blockIdx.y * 64;
    const u32 rawb = smem_u32(&raw[0][0]);

    // prefetch both 32-k W chunks (64 rows x 32 floats each), separate groups
#pragma unroll
    for (int c = 0; c < 2; ++c) {
        const int kb = k0 + c * 32;
#pragma unroll
        for (int i = 0; i < 4; ++i) {
            int u = tid + i * 128;
            int row = u >> 3, g = u & 7;
            CP_ASYNC16(rawb + (u32)(c * 64 * KA_RAWS + row * KA_RAWS + g * 4) * 4,
                       W + (size_t)(p0 + row) * PRE_ + kb + g * 4);
        }
        CP_COMMIT();
    }

    // stage x tile [32 b][64 k] as exact tf32
    {
        const int b = tid >> 2, kseg = (tid & 3) * 16;
        const float4* xr = reinterpret_cast<const float4*>(x + b * PRE_ + k0 + kseg);
#pragma unroll
        for (int j = 0; j < 4; ++j) {
            float4 v = xr[j];
            xs[b * KA_XSS + kseg + j * 4 + 0] = cvt_tf32(v.x);
            xs[b * KA_XSS + kseg + j * 4 + 1] = cvt_tf32(v.y);
            xs[b * KA_XSS + kseg + j * 4 + 2] = cvt_tf32(v.z);
            xs[b * KA_XSS + kseg + j * 4 + 3] = cvt_tf32(v.w);
        }
    }

    float acc[2][2][4];   // [mf(b half)][nf(8p group)][reg]
#pragma unroll
    for (int i = 0; i < 2; ++i)
#pragma unroll
        for (int j = 0; j < 2; ++j)
#pragma unroll
            for (int r = 0; r < 4; ++r) acc[i][j][r] = 0.0f;

#pragma unroll
    for (int c = 0; c < 2; ++c) {
        if (c == 0) { CP_WAIT(1); } else { CP_WAIT(0); }
        __syncthreads();
        const float* rb = &raw[c][0];
#pragma unroll
        for (int ks = 0; ks < 4; ++ks) {
            const int kc = ks * 8;
            const int kx = c * 32 + kc;
            // A fragments (x, exact tf32)
            u32 a[2][4];
#pragma unroll
            for (int mf = 0; mf < 2; ++mf) {
                const int r0 = mf * 16 + gid;
                a[mf][0] = xs[r0 * KA_XSS + kx + tig];
                a[mf][1] = xs[(r0 + 8) * KA_XSS + kx + tig];
                a[mf][2] = xs[r0 * KA_XSS + kx + tig + 4];
                a[mf][3] = xs[(r0 + 8) * KA_XSS + kx + tig + 4];
            }
            // B fragments: 2 p-groups, fp32 -> (hi, lo) tf32 in registers
#pragma unroll
            for (int nf = 0; nf < 2; ++nf) {
                const int n = wid * 16 + nf * 8 + gid;
                float w0 = rb[n * KA_RAWS + kc + tig];
                float w1 = rb[n * KA_RAWS + kc + tig + 4];
                u32 h0 = cvt_tf32(w0), h1 = cvt_tf32(w1);
                u32 l0 = cvt_tf32(w0 - __uint_as_float(h0));
                u32 l1 = cvt_tf32(w1 - __uint_as_float(h1));
                mma1688tf32(acc[0][nf], a[0], h0, h1);
                mma1688tf32(acc[1][nf], a[1], h0, h1);
                mma1688tf32(acc[0][nf], a[0], l0, l1);
                mma1688tf32(acc[1][nf], a[1], l0, l1);
            }
        }
    }

    // epilogue: partials g_part[split][b][p]
    float* pp = g_part + (size_t)blockIdx.y * (B_ * POST_);
#pragma unroll
    for (int mf = 0; mf < 2; ++mf)
#pragma unroll
        for (int nf = 0; nf < 2; ++nf) {
            const int p = p0 + wid * 16 + nf * 8 + tig * 2;
            const int b = mf * 16 + gid;
            *reinterpret_cast<float2*>(&pp[(size_t)b * POST_ + p]) =
                make_float2(acc[mf][nf][0], acc[mf][nf][1]);
            *reinterpret_cast<float2*>(&pp[(size_t)(b + 8) * POST_ + p]) =
                make_float2(acc[mf][nf][2], acc[mf][nf][3]);
        }
}

// =============================================================================
// kBP: fused reduce + spike + traces + operand packing. grid 64 x 256 thr,
// 32 columns of both packs per block.
//  A[p][kk]: 0-31 & 32-63 = spike ; 64-95 = hi(tqn) ; 96-127 = lo(tqn)
//  B[q][kk]: 0-31 = hi(tp) ; 32-63 = lo(tp) ; 64-95 & 96-127 = x
// =============================================================================
__global__ __launch_bounds__(256) void kBP(const float* __restrict__ x,
                                           const float* __restrict__ tpre,
                                           const float* __restrict__ tpost,
                                           float* __restrict__ out_spike) {
    __shared__ float sp[32][36], tq[32][36], tp[32][36], xsm[32][36];
    const int tid = threadIdx.x;
    const int c0 = blockIdx.x * 32;

#pragma unroll
    for (int r = 0; r < 4; ++r) {
        int u = tid + r * 256;
        int b = u >> 5, j = u & 31;
        int gi = b * 2048 + c0 + j;
        float s = 0.0f;
#pragma unroll
        for (int k = 0; k < KSPL; ++k) s += g_part[(size_t)k * (B_ * POST_) + gi];
        float spike = (s >= 1.0f) ? 1.0f : 0.0f;
        out_spike[gi] = spike;
        sp[b][j] = spike;
        tq[b][j] = -(0.5f * tpost[gi] + spike);
        float xv = x[gi];
        xsm[b][j] = xv;
        tp[b][j]  = 0.5f * tpre[gi] + xv;
    }
    __syncthreads();

#pragma unroll
    for (int r = 0; r < 4; ++r) {
        int u = tid + r * 256;
        int rr = u >> 5, c4 = u & 31;
        int reg = c4 >> 3, bs = (c4 & 7) * 4;
        BV4 oA, oB;
#pragma unroll
        for (int t = 0; t < 4; ++t) {
            int b = bs + t;
            if (reg < 2) oA.v[t] = __float2bfloat16(sp[b][rr]);
            else {
                float v = tq[b][rr];
                __nv_bfloat16 h = __float2bfloat16(v);
                oA.v[t] = (reg == 2) ? h : __float2bfloat16(v - __bfloat162float(h));
            }
            if (reg >= 2) oB.v[t] = __float2bfloat16(xsm[b][rr]);
            else {
                float v = tp[b][rr];
                __nv_bfloat16 h = __float2bfloat16(v);
                oB.v[t] = (reg == 0) ? h : __float2bfloat16(v - __bfloat162float(h));
            }
        }
        *reinterpret_cast<BV4*>(&g_Apack[(size_t)(c0 + rr) * 128 + c4 * 4]) = oA;
        *reinterpret_cast<BV4*>(&g_Bpack[(size_t)(c0 + rr) * 128 + c4 * 4]) = oB;
    }
}

// =============================================================================
// kC: dw = clip(W) * (Apack @ Bpack^T), K=128 bf16 HMMA.
// grid (16, 16) = 256 CTAs (single wave at 2/SM), 256 thr.
// Tile 128p x 128q; warps 2(p) x 4(q), warp tile 64p x 32q (mf=4, nf=4).
// Packs loaded as two K-half cp.async groups (MMA on half0 overlaps half1).
// W read directly from global in the epilogue (sector-aligned float2 LDG).
// =============================================================================
#define KC_AS   136                         // pack tile stride (bf16)
#define KC_TB   (128 * KC_AS * 2)           // 34816 B per tile
#define KC_SMEM (2 * KC_TB)                 // 69632 B

__global__ __launch_bounds__(256, 2) void kC(const float* __restrict__ W,
                                             float* __restrict__ dw) {
    extern __shared__ char smc[];
    __nv_bfloat16* As = reinterpret_cast<__nv_bfloat16*>(smc);
    __nv_bfloat16* Bs = reinterpret_cast<__nv_bfloat16*>(smc + KC_TB);
    const u32 sb = smem_u32(smc);

    const int tid = threadIdx.x, wid = tid >> 5, lane = tid & 31;
    const int gid = lane >> 2, tig = lane & 3;
    const int pw = wid >> 2, qw = wid & 3;
    const int p0 = blockIdx.x * 128, q0 = blockIdx.y * 128;

    // group 1: K-half 0 of both packs (bytes 0..127 of each 256B row)
#pragma unroll
    for (int i = 0; i < 4; ++i) {
        int u = tid + i * 256;
        int row = u >> 3, g = u & 7;
        CP_ASYNC16(sb + (u32)(row * KC_AS * 2 + g * 16),
                   g_Apack + (size_t)(p0 + row) * 128 + g * 8);
        CP_ASYNC16(sb + KC_TB + (u32)(row * KC_AS * 2 + g * 16),
                   g_Bpack + (size_t)(q0 + row) * 128 + g * 8);
    }
    CP_COMMIT();
    // group 2: K-half 1
#pragma unroll
    for (int i = 0; i < 4; ++i) {
        int u = tid + i * 256;
        int row = u >> 3, g = (u & 7) + 8;
        CP_ASYNC16(sb + (u32)(row * KC_AS * 2 + g * 16),
                   g_Apack + (size_t)(p0 + row) * 128 + g * 8);
        CP_ASYNC16(sb + KC_TB + (u32)(row * KC_AS * 2 + g * 16),
                   g_Bpack + (size_t)(q0 + row) * 128 + g * 8);
    }
    CP_COMMIT();

    float acc[4][4][4];   // [mf][nf][reg]
#pragma unroll
    for (int i = 0; i < 4; ++i)
#pragma unroll
        for (int j = 0; j < 4; ++j)
#pragma unroll
            for (int r = 0; r < 4; ++r) acc[i][j][r] = 0.0f;

#pragma unroll
    for (int h = 0; h < 2; ++h) {
        if (h == 0) { CP_WAIT(1); } else { CP_WAIT(0); }
        __syncthreads();
#pragma unroll
        for (int kk = 0; kk < 4; ++kk) {
            const int kc = h * 64 + kk * 16 + tig * 2;
            u32 a[4][4];
#pragma unroll
            for (int mf = 0; mf < 4; ++mf) {
                const int r0 = pw * 64 + mf * 16 + gid;
                a[mf][0] = *reinterpret_cast<const u32*>(&As[r0 * KC_AS + kc]);
                a[mf][1] = *reinterpret_cast<const u32*>(&As[(r0 + 8) * KC_AS + kc]);
                a[mf][2] = *reinterpret_cast<const u32*>(&As[r0 * KC_AS + kc + 8]);
                a[mf][3] = *reinterpret_cast<const u32*>(&As[(r0 + 8) * KC_AS + kc + 8]);
            }
#pragma unroll
            for (int nf = 0; nf < 4; ++nf) {
                const int n = qw * 32 + nf * 8 + gid;
                u32 b[2];
                b[0] = *reinterpret_cast<const u32*>(&Bs[n * KC_AS + kc]);
                b[1] = *reinterpret_cast<const u32*>(&Bs[n * KC_AS + kc + 8]);
#pragma unroll
                for (int mf = 0; mf < 4; ++mf) mma16816(acc[mf][nf], a[mf], b);
            }
        }
    }

    // epilogue: clip(W)*acc -> dw; W via direct sector-aligned LDG
#pragma unroll
    for (int mf = 0; mf < 4; ++mf)
#pragma unroll
        for (int nf = 0; nf < 4; ++nf) {
            const int p = p0 + pw * 64 + mf * 16 + gid;
            const int q = q0 + qw * 32 + nf * 8 + tig * 2;
            float2 w0 = *reinterpret_cast<const float2*>(&W[(size_t)p * PRE_ + q]);
            float2 w1 = *reinterpret_cast<const float2*>(&W[(size_t)(p + 8) * PRE_ + q]);
            float2 o0, o1;
            o0.x = fminf(fmaxf(w0.x, -1.f), 1.f) * acc[mf][nf][0];
            o0.y = fminf(fmaxf(w0.y, -1.f), 1.f) * acc[mf][nf][1];
            o1.x = fminf(fmaxf(w1.x, -1.f), 1.f) * acc[mf][nf][2];
            o1.y = fminf(fmaxf(w1.y, -1.f), 1.f) * acc[mf][nf][3];
            *reinterpret_cast<float2*>(&dw[(size_t)p * PRE_ + q])       = o0;
            *reinterpret_cast<float2*>(&dw[(size_t)(p + 8) * PRE_ + q]) = o1;
        }
}

// =============================================================================
extern "C" void kernel_launch(void* const* d_in, const int* in_sizes, int n_in,
                              void* d_out, int out_size) {
    const float* x     = (const float*)d_in[0];   // [32, 2048]
    const float* W     = (const float*)d_in[1];   // [2048, 2048]
    const float* tpre  = (const float*)d_in[2];   // [32, 2048]
    const float* tpost = (const float*)d_in[3];   // [32, 2048]
    float* out     = (float*)d_out;
    float* spike_o = out;                         // [32, 2048]
    float* dw_o    = out + B_ * POST_;            // [2048, 2048]

    cudaFuncSetAttribute(kC, cudaFuncAttributeMaxDynamicSharedMemorySize, KC_SMEM);

    kA<<<dim3(POST_ / 64, KSPL), 128>>>(x, W);
    kBP<<<64, 256>>>(x, tpre, tpost, spike_o);
    kC<<<dim3(POST_ / 128, PRE_ / 128), 256, KC_SMEM>>>(W, dw_o);
}